// round 16
// baseline (speedup 1.0000x reference)
#include <cuda_runtime.h>
#include <cstdint>

#define N_PDE   4096
#define WINDOW  327
#define HALF    163
#define TB      16                 // starts per phase-B block
#define NBLK_B  (N_PDE / TB)       // 256
#define HS      260                // hbuf stride (float4-aligned, conflict-free)
#define KSUB    4                  // table samples per xi-bin
#define NTAB    (N_PDE * KSUB)     // 16384 table entries
#define EPAD    384                // padded error buffer size
#define ESZ     (EPAD + TB)        // e[] / ecd[] length (400)

// Scratch (allocation-free rule: __device__ globals)
__device__ float  g_R20[20 * 327];     // normalized resize rows
__device__ float  g_hc[N_PDE * 32];    // branch output folded through cW[:256] (+cb)
__device__ float2 g_tab[NTAB];         // (u,v) final outputs on the xi grid

// ---------------------------------------------------------------------------
// helpers
// ---------------------------------------------------------------------------
__device__ __forceinline__ float2 fma2(float2 a, float2 b, float2 c) {
    float2 d;
    asm("{\n\t"
        ".reg .b64 ra, rb, rc, rd;\n\t"
        "mov.b64 ra, {%2,%3};\n\t"
        "mov.b64 rb, {%4,%5};\n\t"
        "mov.b64 rc, {%6,%7};\n\t"
        "fma.rn.f32x2 rd, ra, rb, rc;\n\t"
        "mov.b64 {%0,%1}, rd;\n\t"
        "}"
        : "=f"(d.x), "=f"(d.y)
        : "f"(a.x), "f"(a.y), "f"(b.x), "f"(b.y), "f"(c.x), "f"(c.y));
    return d;
}

__device__ __forceinline__ float tanh_mufu(float x) {
    float y;
    asm("tanh.approx.f32 %0, %1;" : "=f"(y) : "f"(x));
    return y;
}

__device__ __forceinline__ float warp_sum(float v) {
    #pragma unroll
    for (int o = 16; o > 0; o >>= 1) v += __shfl_xor_sync(0xffffffffu, v, o);
    return v;
}

#define RSCALE     (20.0f / 327.0f)
#define RINVSCALE  (327.0f / 20.0f)

// triangle kernel tap (antialiased bilinear downsample), unnormalized
__device__ __forceinline__ float tri(int o, float i) {
    float sf = ((float)o + 0.5f) * RINVSCALE - 0.5f;
    float x  = fabsf(sf - i) * RSCALE;
    return fmaxf(0.0f, 1.0f - x);
}

// ---------------------------------------------------------------------------
// Setup: normalized resize rows into global. grid=20 blocks x 128 thr.
// ---------------------------------------------------------------------------
__global__ __launch_bounds__(128) void phaseR_kernel() {
    __shared__ float ws[4];
    const int tid = threadIdx.x, lane = tid & 31, w = tid >> 5;
    const int o = blockIdx.x;
    float s = 0.0f;
    for (int i = tid; i < 327; i += 128) s += tri(o, (float)i);
    s = warp_sum(s);
    if (lane == 0) ws[w] = s;
    __syncthreads();
    float inv = 1.0f / (ws[0] + ws[1] + ws[2] + ws[3]);
    for (int i = tid; i < 327; i += 128)
        g_R20[o * 327 + i] = tri(o, (float)i) * inv;
}

// ---------------------------------------------------------------------------
// Phase B: per distinct start s (4096 total), branch net folded through
// cW[:256] (+cb) into g_hc[s][32]. TB=16 starts/block, 256 threads,
// one feature per thread — halves weight traffic vs TB=8.
// ---------------------------------------------------------------------------
__global__ __launch_bounds__(256, 2) void phaseB_kernel(
    const float* __restrict__ z, const float* __restrict__ zt,
    const float* __restrict__ bW0, const float* __restrict__ bb0,
    const float* __restrict__ bs0, const float* __restrict__ bB0,
    const float* __restrict__ bW1, const float* __restrict__ bb1,
    const float* __restrict__ bs1, const float* __restrict__ bB1,
    const float* __restrict__ cW,  const float* __restrict__ cb)
{
    __shared__ float e[ESZ];               // sliding error window (edge-padded)
    __shared__ float ecd[ESZ];             // central diff of e (shared over t)
    __shared__ float obs[TB * 40];
    __shared__ float hbuf[TB * HS];        // padded stride HS (float4-aligned)
    __shared__ float mu_s[TB], rs_s[TB];

    const int tid = threadIdx.x;
    const int w = tid >> 5, lane = tid & 31;
    const int s0  = blockIdx.x * TB;

    // padded error: e[j] = error[clamp(s0 + j - HALF, 0, N_PDE-1)]
    for (int j = tid; j < ESZ; j += 256) {
        int c = s0 + j - HALF;
        c = min(max(c, 0), N_PDE - 1);
        e[j] = z[c] - zt[c];
    }
    __syncthreads();

    // central diff (clamped ends; end values cancel in the fixups)
    for (int j = tid; j < ESZ; j += 256) {
        int jm = max(j - 1, 0), jp = min(j + 1, ESZ - 1);
        ecd[j] = 0.5f * (e[jp] - e[jm]);
    }
    __syncthreads();

    // obs: 320 (t,p) pairs over 256 threads; each produces obs[t][p] (resize)
    // and obs[t][20+p] (gradient) with the SAME 34-tap weight row.
    for (int pi = tid; pi < TB * 20; pi += 256) {
        int t = pi / 20, p = pi - 20 * (pi / 20);
        float sf = ((float)p + 0.5f) * RINVSCALE - 0.5f;
        int base = max(0, (int)ceilf(sf - RINVSCALE));
        const float* Rp = g_R20 + p * 327;
        float accR = 0.0f, accG = 0.0f;
        #pragma unroll 2
        for (int m = 0; m < 34; m++) {
            int i = base + m;
            float wv = (i < 327) ? Rp[i] : 0.0f;
            accR = fmaf(wv, e[t + i],   accR);
            accG = fmaf(wv, ecd[t + i], accG);
        }
        if (p == 0) {                      // one-sided diff at window start
            accG += Rp[0] * ((e[t + 1] - e[t]) - ecd[t]);
        }
        if (p == 19) {                     // one-sided diff at window end
            accG += Rp[326] * ((e[t + 326] - e[t + 325]) - ecd[t + 326]);
        }
        obs[t * 40 + p]      = accR;
        obs[t * 40 + 20 + p] = accG;
    }
    __syncthreads();

    float accS[TB];

    // branch layer 0: 40 -> 256, 1 feature per thread, f32x2 over k-pairs
    {
        float2 a2[TB];
        #pragma unroll
        for (int t = 0; t < TB; t++) a2[t] = make_float2(0.0f, 0.0f);
        #pragma unroll 4
        for (int kk = 0; kk < 20; kk++) {
            float2 w2 = make_float2(bW0[(2 * kk) * 256 + tid],
                                    bW0[(2 * kk + 1) * 256 + tid]);
            #pragma unroll
            for (int t = 0; t < TB; t++) {
                float2 ov = *reinterpret_cast<const float2*>(&obs[t * 40 + 2 * kk]);
                a2[t] = fma2(ov, w2, a2[t]);
            }
        }
        float b = bb0[tid];
        #pragma unroll
        for (int t = 0; t < TB; t++) accS[t] = a2[t].x + a2[t].y + b;
    }

    // GroupNorm + tanh (layer 0): warp w reduces samples w and w+8
    {
        #pragma unroll
        for (int t = 0; t < TB; t++) hbuf[t * HS + tid] = accS[t];
        __syncthreads();
        #pragma unroll
        for (int rep = 0; rep < 2; rep++) {
            int tt = w + 8 * rep;
            float s = 0.0f;
            #pragma unroll
            for (int m = 0; m < 8; m++) s += hbuf[tt * HS + lane + 32 * m];
            s = warp_sum(s);
            float mu = s * (1.0f / 256.0f);
            float q = 0.0f;
            #pragma unroll
            for (int m = 0; m < 8; m++) {
                float d = hbuf[tt * HS + lane + 32 * m] - mu;
                q = fmaf(d, d, q);
            }
            q = warp_sum(q);
            if (lane == 0) {
                mu_s[tt] = mu;
                rs_s[tt] = rsqrtf(q * (1.0f / 256.0f) + 1e-6f);
            }
        }
        __syncthreads();
        float sc = bs0[tid], bi = bB0[tid];
        #pragma unroll
        for (int t = 0; t < TB; t++)
            hbuf[t * HS + tid] = tanh_mufu(fmaf((accS[t] - mu_s[t]) * rs_s[t], sc, bi));
        __syncthreads();
    }

    // branch layer 1: 256 -> 256, float4 LDS, 4 weight LDG per 32 fma2
    {
        float2 a2[TB];
        #pragma unroll
        for (int t = 0; t < TB; t++) a2[t] = make_float2(0.0f, 0.0f);
        #pragma unroll 2
        for (int k4 = 0; k4 < 64; k4++) {
            int k = 4 * k4;
            float2 w01 = make_float2(bW1[(k + 0) * 256 + tid], bW1[(k + 1) * 256 + tid]);
            float2 w23 = make_float2(bW1[(k + 2) * 256 + tid], bW1[(k + 3) * 256 + tid]);
            #pragma unroll
            for (int t = 0; t < TB; t++) {
                float4 hv = *reinterpret_cast<const float4*>(&hbuf[t * HS + k]);
                a2[t] = fma2(make_float2(hv.x, hv.y), w01, a2[t]);
                a2[t] = fma2(make_float2(hv.z, hv.w), w23, a2[t]);
            }
        }
        __syncthreads();                   // done reading h0 before gn overwrites
        float b = bb1[tid];
        #pragma unroll
        for (int t = 0; t < TB; t++) accS[t] = a2[t].x + a2[t].y + b;
    }

    // GroupNorm + tanh (layer 1)
    {
        #pragma unroll
        for (int t = 0; t < TB; t++) hbuf[t * HS + tid] = accS[t];
        __syncthreads();
        #pragma unroll
        for (int rep = 0; rep < 2; rep++) {
            int tt = w + 8 * rep;
            float s = 0.0f;
            #pragma unroll
            for (int m = 0; m < 8; m++) s += hbuf[tt * HS + lane + 32 * m];
            s = warp_sum(s);
            float mu = s * (1.0f / 256.0f);
            float q = 0.0f;
            #pragma unroll
            for (int m = 0; m < 8; m++) {
                float d = hbuf[tt * HS + lane + 32 * m] - mu;
                q = fmaf(d, d, q);
            }
            q = warp_sum(q);
            if (lane == 0) {
                mu_s[tt] = mu;
                rs_s[tt] = rsqrtf(q * (1.0f / 256.0f) + 1e-6f);
            }
        }
        __syncthreads();
        float sc = bs1[tid], bi = bB1[tid];
        #pragma unroll
        for (int t = 0; t < TB; t++)
            hbuf[t * HS + tid] = tanh_mufu(fmaf((accS[t] - mu_s[t]) * rs_s[t], sc, bi));
        __syncthreads();
    }

    // fold through cW[:256] (+cb): g_hc[s][o] = h1 . cW[:,o] + cb[o]
    // 512 (t,o) pairs over 256 threads: 2 each.
    {
        #pragma unroll
        for (int rep = 0; rep < 2; rep++) {
            int idx = tid + 256 * rep;
            int t = idx >> 5, o = idx & 31;
            float2 a2f = make_float2(0.0f, 0.0f);
            #pragma unroll 4
            for (int k4 = 0; k4 < 64; k4++) {
                int k = 4 * k4;
                float4 hv = *reinterpret_cast<const float4*>(&hbuf[t * HS + k]);
                float c0 = cW[(k + 0) * 32 + o], c1 = cW[(k + 1) * 32 + o];
                float c2 = cW[(k + 2) * 32 + o], c3 = cW[(k + 3) * 32 + o];
                a2f = fma2(make_float2(hv.x, hv.y), make_float2(c0, c1), a2f);
                a2f = fma2(make_float2(hv.z, hv.w), make_float2(c2, c3), a2f);
            }
            g_hc[(s0 + t) * 32 + o] = a2f.x + a2f.y + cb[o];
        }
    }
}

// ---------------------------------------------------------------------------
// Phase T: tabulate final (u,v) on the xi grid: entry e = (s, k),
// xi = (s + k/3)/4095, branch part = g_hc[s]. Warp per entry, lane = neuron.
// ---------------------------------------------------------------------------
__global__ __launch_bounds__(256) void phaseT_kernel(
    const float* __restrict__ tW0, const float* __restrict__ tb0,
    const float* __restrict__ tW1, const float* __restrict__ tb1,
    const float* __restrict__ cW,
    const float* __restrict__ uW,  const float* __restrict__ ub,
    const float* __restrict__ vW,  const float* __restrict__ vb)
{
    __shared__ float sW0[8 * 32];      // [k*32+j]
    __shared__ float sW1[32 * 32];     // [k*32+j]
    __shared__ float sCt[32 * 32];     // [k*32+j] = cW[(256+k)*32+j]
    __shared__ float sb0[32], sb1[32], suW[32], svW[32];
    __shared__ float subb, svbb;

    const int tid = threadIdx.x, lane = tid & 31, wp = tid >> 5;
    if (tid < 256) {
        sW0[tid] = tW0[tid];
        if (tid < 32) {
            sb0[tid] = tb0[tid]; sb1[tid] = tb1[tid];
            suW[tid] = uW[tid];  svW[tid] = vW[tid];
        }
        if (tid == 0) { subb = ub[0]; svbb = vb[0]; }
    }
    for (int i = tid; i < 1024; i += 256) {
        sW1[i] = tW1[i];
        sCt[i] = cW[256 * 32 + i];
    }
    __syncthreads();

    int e = blockIdx.x * 8 + wp;
    if (e >= NTAB) return;
    int s = e >> 2, k = e & 3;
    float xi = ((float)s + (float)k * (1.0f / 3.0f)) * (1.0f / 4095.0f);

    const float PI = 3.14159265358979323846f;
    float p = xi * PI;
    float enc[8];
    enc[0] = __sinf(p);        enc[1] = __sinf(2.0f * p);
    enc[2] = __sinf(4.0f * p); enc[3] = __sinf(8.0f * p);
    enc[4] = __cosf(p);        enc[5] = __cosf(2.0f * p);
    enc[6] = __cosf(4.0f * p); enc[7] = __cosf(8.0f * p);

    int j = lane;
    float acc = sb0[j];
    #pragma unroll
    for (int kk = 0; kk < 8; kk++) acc = fmaf(enc[kk], sW0[kk * 32 + j], acc);
    float t0 = tanh_mufu(acc);

    acc = sb1[j];
    #pragma unroll
    for (int kk = 0; kk < 32; kk++)
        acc = fmaf(__shfl_sync(0xffffffffu, t0, kk), sW1[kk * 32 + j], acc);
    float t1 = tanh_mufu(acc);

    acc = g_hc[s * 32 + j];          // cb already folded in
    #pragma unroll
    for (int kk = 0; kk < 32; kk++)
        acc = fmaf(__shfl_sync(0xffffffffu, t1, kk), sCt[kk * 32 + j], acc);
    float xo = tanh_mufu(acc);

    float up = warp_sum(xo * suW[j]);
    float vp = warp_sum(xo * svW[j]);
    if (lane == 0)
        g_tab[e] = make_float2(40.0f * tanh_mufu(up + subb),
                               tanh_mufu(vp + svbb));
}

// ---------------------------------------------------------------------------
// Phase I: per-agent linear interpolation; 2 independent agent chains per
// thread at full grid width (keeps occupancy, doubles MLP).
// ---------------------------------------------------------------------------
__global__ __launch_bounds__(256) void phaseI_kernel(
    const float* __restrict__ xi, float* __restrict__ out,
    int nAgents, int halfN)
{
    int a0 = blockIdx.x * 256 + threadIdx.x;
    if (a0 >= halfN) return;
    int a1 = a0 + halfN;
    bool v1 = a1 < nAgents;

    float x0 = xi[a0];
    float x1 = v1 ? xi[a1] : 0.0f;

    float t0f = x0 * 4095.0f;
    float t1f = x1 * 4095.0f;
    int s_0 = (int)t0f, s_1 = (int)t1f;
    float pos0 = (t0f - (float)s_0) * 3.0f;
    float pos1 = (t1f - (float)s_1) * 3.0f;
    int k00 = min((int)pos0, 2), k01 = min((int)pos1, 2);
    float w0 = pos0 - (float)k00, w1 = pos1 - (float)k01;

    float2 p00 = g_tab[s_0 * 4 + k00];
    float2 p01 = g_tab[s_0 * 4 + k00 + 1];
    float2 p10 = g_tab[s_1 * 4 + k01];
    float2 p11 = g_tab[s_1 * 4 + k01 + 1];

    out[a0]           = fmaf(w0, p01.x - p00.x, p00.x);
    out[a0 + nAgents] = fmaf(w0, p01.y - p00.y, p00.y);
    if (v1) {
        out[a1]           = fmaf(w1, p11.x - p10.x, p10.x);
        out[a1 + nAgents] = fmaf(w1, p11.y - p10.y, p10.y);
    }
}

// ---------------------------------------------------------------------------
extern "C" void kernel_launch(void* const* d_in, const int* in_sizes, int n_in,
                              void* d_out, int out_size) {
    const float* z_curr   = (const float*)d_in[0];
    const float* z_target = (const float*)d_in[1];
    const float* xi_curr  = (const float*)d_in[2];
    const float* bW0 = (const float*)d_in[3];
    const float* bb0 = (const float*)d_in[4];
    const float* bs0 = (const float*)d_in[5];
    const float* bB0 = (const float*)d_in[6];
    const float* bW1 = (const float*)d_in[7];
    const float* bb1 = (const float*)d_in[8];
    const float* bs1 = (const float*)d_in[9];
    const float* bB1 = (const float*)d_in[10];
    const float* tW0 = (const float*)d_in[11];
    const float* tb0 = (const float*)d_in[12];
    const float* tW1 = (const float*)d_in[13];
    const float* tb1 = (const float*)d_in[14];
    const float* cW  = (const float*)d_in[15];
    const float* cb  = (const float*)d_in[16];
    const float* uW  = (const float*)d_in[17];
    const float* ub  = (const float*)d_in[18];
    const float* vW  = (const float*)d_in[19];
    const float* vb  = (const float*)d_in[20];

    const int nAgents = in_sizes[2];
    const int halfN = (nAgents + 1) / 2;

    phaseR_kernel<<<20, 128>>>();
    phaseB_kernel<<<NBLK_B, 256>>>(z_curr, z_target,
                                   bW0, bb0, bs0, bB0,
                                   bW1, bb1, bs1, bB1, cW, cb);
    phaseT_kernel<<<NTAB / 8, 256>>>(tW0, tb0, tW1, tb1, cW,
                                     uW, ub, vW, vb);
    phaseI_kernel<<<(halfN + 255) / 256, 256>>>(xi_curr,
                                                (float*)d_out, nAgents, halfN);
}

// round 17
// speedup vs baseline: 1.6881x; 1.6881x over previous
#include <cuda_runtime.h>
#include <cstdint>

#define N_PDE   4096
#define WINDOW  327
#define HALF    163
#define TB      16                 // starts per phase-B block
#define NBLK_B  (N_PDE / TB)       // 256
#define HS      260                // hbuf stride (float4-aligned, conflict-free)
#define KSUB    4                  // table samples per xi-bin
#define NTAB    (N_PDE * KSUB)     // 16384 table entries
#define EPAD    384                // padded error buffer size
#define ESZ     (EPAD + TB)        // e[] / ecd[] length (400)

// Scratch (allocation-free rule: __device__ globals)
__device__ float  g_R20[20 * 327];     // normalized resize rows
__device__ float  g_hc[N_PDE * 32];    // branch output folded through cW[:256] (+cb)
__device__ float2 g_tab[NTAB];         // (u,v) final outputs on the xi grid

// ---------------------------------------------------------------------------
// helpers
// ---------------------------------------------------------------------------
__device__ __forceinline__ float2 fma2(float2 a, float2 b, float2 c) {
    float2 d;
    asm("{\n\t"
        ".reg .b64 ra, rb, rc, rd;\n\t"
        "mov.b64 ra, {%2,%3};\n\t"
        "mov.b64 rb, {%4,%5};\n\t"
        "mov.b64 rc, {%6,%7};\n\t"
        "fma.rn.f32x2 rd, ra, rb, rc;\n\t"
        "mov.b64 {%0,%1}, rd;\n\t"
        "}"
        : "=f"(d.x), "=f"(d.y)
        : "f"(a.x), "f"(a.y), "f"(b.x), "f"(b.y), "f"(c.x), "f"(c.y));
    return d;
}

__device__ __forceinline__ float tanh_mufu(float x) {
    float y;
    asm("tanh.approx.f32 %0, %1;" : "=f"(y) : "f"(x));
    return y;
}

__device__ __forceinline__ float warp_sum(float v) {
    #pragma unroll
    for (int o = 16; o > 0; o >>= 1) v += __shfl_xor_sync(0xffffffffu, v, o);
    return v;
}

#define RSCALE     (20.0f / 327.0f)
#define RINVSCALE  (327.0f / 20.0f)

// triangle kernel tap (antialiased bilinear downsample), unnormalized
__device__ __forceinline__ float tri(int o, float i) {
    float sf = ((float)o + 0.5f) * RINVSCALE - 0.5f;
    float x  = fabsf(sf - i) * RSCALE;
    return fmaxf(0.0f, 1.0f - x);
}

// ---------------------------------------------------------------------------
// Setup: normalized resize rows into global. grid=20 blocks x 128 thr.
// ---------------------------------------------------------------------------
__global__ __launch_bounds__(128) void phaseR_kernel() {
    __shared__ float ws[4];
    const int tid = threadIdx.x, lane = tid & 31, w = tid >> 5;
    const int o = blockIdx.x;
    float s = 0.0f;
    for (int i = tid; i < 327; i += 128) s += tri(o, (float)i);
    s = warp_sum(s);
    if (lane == 0) ws[w] = s;
    __syncthreads();
    float inv = 1.0f / (ws[0] + ws[1] + ws[2] + ws[3]);
    for (int i = tid; i < 327; i += 128)
        g_R20[o * 327 + i] = tri(o, (float)i) * inv;
}

// ---------------------------------------------------------------------------
// Phase B: per distinct start s (4096 total), branch net folded through
// cW[:256] (+cb) into g_hc[s][32]. TB=16 starts/block, 256 threads:
// thread (sh = tid>>7, f = tid&127) computes features (f, f+128) for its
// 8 samples sh*8..sh*8+7. Per-thread shape identical to the proven TB=8
// layout; weight reads amortized over 2x the samples (sh=1 hits L1).
// ---------------------------------------------------------------------------
__global__ __launch_bounds__(256, 2) void phaseB_kernel(
    const float* __restrict__ z, const float* __restrict__ zt,
    const float* __restrict__ bW0, const float* __restrict__ bb0,
    const float* __restrict__ bs0, const float* __restrict__ bB0,
    const float* __restrict__ bW1, const float* __restrict__ bb1,
    const float* __restrict__ bs1, const float* __restrict__ bB1,
    const float* __restrict__ cW,  const float* __restrict__ cb)
{
    __shared__ float e[ESZ];               // sliding error window (edge-padded)
    __shared__ float ecd[ESZ];             // central diff of e (shared over t)
    __shared__ float obs[TB * 40];
    __shared__ float hbuf[TB * HS];        // padded stride HS (float4-aligned)
    __shared__ float mu_s[TB], rs_s[TB];

    const int tid = threadIdx.x;
    const int w = tid >> 5, lane = tid & 31;
    const int f  = tid & 127;              // feature (also f+128)
    const int tb0i = (tid >> 7) * 8;       // first sample of this thread's half
    const int s0  = blockIdx.x * TB;

    // padded error: e[j] = error[clamp(s0 + j - HALF, 0, N_PDE-1)]
    for (int j = tid; j < ESZ; j += 256) {
        int c = s0 + j - HALF;
        c = min(max(c, 0), N_PDE - 1);
        e[j] = z[c] - zt[c];
    }
    __syncthreads();

    // central diff (clamped ends; end values cancel in the fixups)
    for (int j = tid; j < ESZ; j += 256) {
        int jm = max(j - 1, 0), jp = min(j + 1, ESZ - 1);
        ecd[j] = 0.5f * (e[jp] - e[jm]);
    }
    __syncthreads();

    // obs: 320 (t,p) pairs over 256 threads; each produces obs[t][p] (resize)
    // and obs[t][20+p] (gradient) with the SAME 34-tap weight row.
    for (int pi = tid; pi < TB * 20; pi += 256) {
        int t = pi / 20, p = pi - 20 * (pi / 20);
        float sf = ((float)p + 0.5f) * RINVSCALE - 0.5f;
        int base = max(0, (int)ceilf(sf - RINVSCALE));
        const float* Rp = g_R20 + p * 327;
        float accR = 0.0f, accG = 0.0f;
        #pragma unroll 2
        for (int m = 0; m < 34; m++) {
            int i = base + m;
            float wv = (i < 327) ? Rp[i] : 0.0f;
            accR = fmaf(wv, e[t + i],   accR);
            accG = fmaf(wv, ecd[t + i], accG);
        }
        if (p == 0) {                      // one-sided diff at window start
            accG += Rp[0] * ((e[t + 1] - e[t]) - ecd[t]);
        }
        if (p == 19) {                     // one-sided diff at window end
            accG += Rp[326] * ((e[t + 326] - e[t + 325]) - ecd[t + 326]);
        }
        obs[t * 40 + p]      = accR;
        obs[t * 40 + 20 + p] = accG;
    }
    __syncthreads();

    float accA[8], accB[8];

    // branch layer 0: 40 -> 256, 2 features x 8 samples per thread
    {
        float2 aA[8], aB[8];
        #pragma unroll
        for (int t = 0; t < 8; t++) {
            aA[t] = make_float2(0.0f, 0.0f);
            aB[t] = make_float2(0.0f, 0.0f);
        }
        #pragma unroll 4
        for (int kk = 0; kk < 20; kk++) {
            const float* w0 = bW0 + (2 * kk) * 256;
            const float* w1 = bW0 + (2 * kk + 1) * 256;
            float2 wA = make_float2(w0[f],       w1[f]);
            float2 wB = make_float2(w0[f + 128], w1[f + 128]);
            #pragma unroll
            for (int t = 0; t < 8; t++) {
                float2 ov = *reinterpret_cast<const float2*>(&obs[(tb0i + t) * 40 + 2 * kk]);
                aA[t] = fma2(ov, wA, aA[t]);
                aB[t] = fma2(ov, wB, aB[t]);
            }
        }
        float bA = bb0[f], bB = bb0[f + 128];
        #pragma unroll
        for (int t = 0; t < 8; t++) {
            accA[t] = aA[t].x + aA[t].y + bA;
            accB[t] = aB[t].x + aB[t].y + bB;
        }
    }

    // GroupNorm + tanh (layer 0): 16 samples, warp w reduces t = w and w+8
    {
        #pragma unroll
        for (int t = 0; t < 8; t++) {
            hbuf[(tb0i + t) * HS + f]       = accA[t];
            hbuf[(tb0i + t) * HS + f + 128] = accB[t];
        }
        __syncthreads();
        #pragma unroll
        for (int rep = 0; rep < 2; rep++) {
            int tt = w + 8 * rep;
            float s = 0.0f;
            #pragma unroll
            for (int m = 0; m < 8; m++) s += hbuf[tt * HS + lane + 32 * m];
            s = warp_sum(s);
            float mu = s * (1.0f / 256.0f);
            float q = 0.0f;
            #pragma unroll
            for (int m = 0; m < 8; m++) {
                float d = hbuf[tt * HS + lane + 32 * m] - mu;
                q = fmaf(d, d, q);
            }
            q = warp_sum(q);
            if (lane == 0) {
                mu_s[tt] = mu;
                rs_s[tt] = rsqrtf(q * (1.0f / 256.0f) + 1e-6f);
            }
        }
        __syncthreads();
        float scA = bs0[f], biA = bB0[f];
        float scB = bs0[f + 128], biB = bB0[f + 128];
        #pragma unroll
        for (int t = 0; t < 8; t++) {
            float mu = mu_s[tb0i + t], rs = rs_s[tb0i + t];
            hbuf[(tb0i + t) * HS + f]       = tanh_mufu(fmaf((accA[t] - mu) * rs, scA, biA));
            hbuf[(tb0i + t) * HS + f + 128] = tanh_mufu(fmaf((accB[t] - mu) * rs, scB, biB));
        }
        __syncthreads();
    }

    // branch layer 1: 256 -> 256; per-thread shape = proven TB=8 layout
    {
        float2 aA[8], aB[8];
        #pragma unroll
        for (int t = 0; t < 8; t++) {
            aA[t] = make_float2(0.0f, 0.0f);
            aB[t] = make_float2(0.0f, 0.0f);
        }
        #pragma unroll 2
        for (int k4 = 0; k4 < 64; k4++) {
            int k = 4 * k4;
            const float* r0 = bW1 + (k + 0) * 256;
            const float* r1 = bW1 + (k + 1) * 256;
            const float* r2 = bW1 + (k + 2) * 256;
            const float* r3 = bW1 + (k + 3) * 256;
            float2 wA01 = make_float2(r0[f], r1[f]);
            float2 wA23 = make_float2(r2[f], r3[f]);
            float2 wB01 = make_float2(r0[f + 128], r1[f + 128]);
            float2 wB23 = make_float2(r2[f + 128], r3[f + 128]);
            #pragma unroll
            for (int t = 0; t < 8; t++) {
                float4 hv = *reinterpret_cast<const float4*>(&hbuf[(tb0i + t) * HS + k]);
                float2 hxy = make_float2(hv.x, hv.y);
                float2 hzw = make_float2(hv.z, hv.w);
                aA[t] = fma2(hxy, wA01, aA[t]);
                aA[t] = fma2(hzw, wA23, aA[t]);
                aB[t] = fma2(hxy, wB01, aB[t]);
                aB[t] = fma2(hzw, wB23, aB[t]);
            }
        }
        __syncthreads();                   // done reading h0 before gn overwrites
        float bA = bb1[f], bB = bb1[f + 128];
        #pragma unroll
        for (int t = 0; t < 8; t++) {
            accA[t] = aA[t].x + aA[t].y + bA;
            accB[t] = aB[t].x + aB[t].y + bB;
        }
    }

    // GroupNorm + tanh (layer 1)
    {
        #pragma unroll
        for (int t = 0; t < 8; t++) {
            hbuf[(tb0i + t) * HS + f]       = accA[t];
            hbuf[(tb0i + t) * HS + f + 128] = accB[t];
        }
        __syncthreads();
        #pragma unroll
        for (int rep = 0; rep < 2; rep++) {
            int tt = w + 8 * rep;
            float s = 0.0f;
            #pragma unroll
            for (int m = 0; m < 8; m++) s += hbuf[tt * HS + lane + 32 * m];
            s = warp_sum(s);
            float mu = s * (1.0f / 256.0f);
            float q = 0.0f;
            #pragma unroll
            for (int m = 0; m < 8; m++) {
                float d = hbuf[tt * HS + lane + 32 * m] - mu;
                q = fmaf(d, d, q);
            }
            q = warp_sum(q);
            if (lane == 0) {
                mu_s[tt] = mu;
                rs_s[tt] = rsqrtf(q * (1.0f / 256.0f) + 1e-6f);
            }
        }
        __syncthreads();
        float scA = bs1[f], biA = bB1[f];
        float scB = bs1[f + 128], biB = bB1[f + 128];
        #pragma unroll
        for (int t = 0; t < 8; t++) {
            float mu = mu_s[tb0i + t], rs = rs_s[tb0i + t];
            hbuf[(tb0i + t) * HS + f]       = tanh_mufu(fmaf((accA[t] - mu) * rs, scA, biA));
            hbuf[(tb0i + t) * HS + f + 128] = tanh_mufu(fmaf((accB[t] - mu) * rs, scB, biB));
        }
        __syncthreads();
    }

    // fold through cW[:256] (+cb): g_hc[s][o] = h1 . cW[:,o] + cb[o]
    // 512 (t,o) pairs over 256 threads: 2 each.
    {
        #pragma unroll
        for (int rep = 0; rep < 2; rep++) {
            int idx = tid + 256 * rep;
            int t = idx >> 5, o = idx & 31;
            float2 a2f = make_float2(0.0f, 0.0f);
            #pragma unroll 4
            for (int k4 = 0; k4 < 64; k4++) {
                int k = 4 * k4;
                float4 hv = *reinterpret_cast<const float4*>(&hbuf[t * HS + k]);
                float c0 = cW[(k + 0) * 32 + o], c1 = cW[(k + 1) * 32 + o];
                float c2 = cW[(k + 2) * 32 + o], c3 = cW[(k + 3) * 32 + o];
                a2f = fma2(make_float2(hv.x, hv.y), make_float2(c0, c1), a2f);
                a2f = fma2(make_float2(hv.z, hv.w), make_float2(c2, c3), a2f);
            }
            g_hc[(s0 + t) * 32 + o] = a2f.x + a2f.y + cb[o];
        }
    }
}

// ---------------------------------------------------------------------------
// Phase T: tabulate final (u,v) on the xi grid: entry e = (s, k),
// xi = (s + k/3)/4095, branch part = g_hc[s]. Warp per entry, lane = neuron.
// ---------------------------------------------------------------------------
__global__ __launch_bounds__(256) void phaseT_kernel(
    const float* __restrict__ tW0, const float* __restrict__ tb0,
    const float* __restrict__ tW1, const float* __restrict__ tb1,
    const float* __restrict__ cW,
    const float* __restrict__ uW,  const float* __restrict__ ub,
    const float* __restrict__ vW,  const float* __restrict__ vb)
{
    __shared__ float sW0[8 * 32];      // [k*32+j]
    __shared__ float sW1[32 * 32];     // [k*32+j]
    __shared__ float sCt[32 * 32];     // [k*32+j] = cW[(256+k)*32+j]
    __shared__ float sb0[32], sb1[32], suW[32], svW[32];
    __shared__ float subb, svbb;

    const int tid = threadIdx.x, lane = tid & 31, wp = tid >> 5;
    if (tid < 256) {
        sW0[tid] = tW0[tid];
        if (tid < 32) {
            sb0[tid] = tb0[tid]; sb1[tid] = tb1[tid];
            suW[tid] = uW[tid];  svW[tid] = vW[tid];
        }
        if (tid == 0) { subb = ub[0]; svbb = vb[0]; }
    }
    for (int i = tid; i < 1024; i += 256) {
        sW1[i] = tW1[i];
        sCt[i] = cW[256 * 32 + i];
    }
    __syncthreads();

    int e = blockIdx.x * 8 + wp;
    if (e >= NTAB) return;
    int s = e >> 2, k = e & 3;
    float xi = ((float)s + (float)k * (1.0f / 3.0f)) * (1.0f / 4095.0f);

    const float PI = 3.14159265358979323846f;
    float p = xi * PI;
    float enc[8];
    enc[0] = __sinf(p);        enc[1] = __sinf(2.0f * p);
    enc[2] = __sinf(4.0f * p); enc[3] = __sinf(8.0f * p);
    enc[4] = __cosf(p);        enc[5] = __cosf(2.0f * p);
    enc[6] = __cosf(4.0f * p); enc[7] = __cosf(8.0f * p);

    int j = lane;
    float acc = sb0[j];
    #pragma unroll
    for (int kk = 0; kk < 8; kk++) acc = fmaf(enc[kk], sW0[kk * 32 + j], acc);
    float t0 = tanh_mufu(acc);

    acc = sb1[j];
    #pragma unroll
    for (int kk = 0; kk < 32; kk++)
        acc = fmaf(__shfl_sync(0xffffffffu, t0, kk), sW1[kk * 32 + j], acc);
    float t1 = tanh_mufu(acc);

    acc = g_hc[s * 32 + j];          // cb already folded in
    #pragma unroll
    for (int kk = 0; kk < 32; kk++)
        acc = fmaf(__shfl_sync(0xffffffffu, t1, kk), sCt[kk * 32 + j], acc);
    float xo = tanh_mufu(acc);

    float up = warp_sum(xo * suW[j]);
    float vp = warp_sum(xo * svW[j]);
    if (lane == 0)
        g_tab[e] = make_float2(40.0f * tanh_mufu(up + subb),
                               tanh_mufu(vp + svbb));
}

// ---------------------------------------------------------------------------
// Phase I: per-agent linear interpolation from the table.
// ---------------------------------------------------------------------------
__global__ __launch_bounds__(256) void phaseI_kernel(
    const float* __restrict__ xi, float* __restrict__ out, int nAgents)
{
    int a = blockIdx.x * 256 + threadIdx.x;
    if (a >= nAgents) return;
    float t = xi[a] * 4095.0f;
    int s = (int)t;                        // same truncation as reference
    float frac = t - (float)s;
    float pos = frac * 3.0f;
    int k0 = min((int)pos, 2);
    float w = pos - (float)k0;
    float2 p0 = g_tab[s * 4 + k0];
    float2 p1 = g_tab[s * 4 + k0 + 1];
    out[a]           = fmaf(w, p1.x - p0.x, p0.x);
    out[a + nAgents] = fmaf(w, p1.y - p0.y, p0.y);
}

// ---------------------------------------------------------------------------
extern "C" void kernel_launch(void* const* d_in, const int* in_sizes, int n_in,
                              void* d_out, int out_size) {
    const float* z_curr   = (const float*)d_in[0];
    const float* z_target = (const float*)d_in[1];
    const float* xi_curr  = (const float*)d_in[2];
    const float* bW0 = (const float*)d_in[3];
    const float* bb0 = (const float*)d_in[4];
    const float* bs0 = (const float*)d_in[5];
    const float* bB0 = (const float*)d_in[6];
    const float* bW1 = (const float*)d_in[7];
    const float* bb1 = (const float*)d_in[8];
    const float* bs1 = (const float*)d_in[9];
    const float* bB1 = (const float*)d_in[10];
    const float* tW0 = (const float*)d_in[11];
    const float* tb0 = (const float*)d_in[12];
    const float* tW1 = (const float*)d_in[13];
    const float* tb1 = (const float*)d_in[14];
    const float* cW  = (const float*)d_in[15];
    const float* cb  = (const float*)d_in[16];
    const float* uW  = (const float*)d_in[17];
    const float* ub  = (const float*)d_in[18];
    const float* vW  = (const float*)d_in[19];
    const float* vb  = (const float*)d_in[20];

    const int nAgents = in_sizes[2];

    phaseR_kernel<<<20, 128>>>();
    phaseB_kernel<<<NBLK_B, 256>>>(z_curr, z_target,
                                   bW0, bb0, bs0, bB0,
                                   bW1, bb1, bs1, bB1, cW, cb);
    phaseT_kernel<<<NTAB / 8, 256>>>(tW0, tb0, tW1, tb1, cW,
                                     uW, ub, vW, vb);
    phaseI_kernel<<<(nAgents + 255) / 256, 256>>>(xi_curr,
                                                  (float*)d_out, nAgents);
}